// round 1
// baseline (speedup 1.0000x reference)
#include <cuda_runtime.h>

// Sparse ConvTranspose3d on GB300:
//   out[r, :] = bias + sum over (k,n) with out_index[k,n]==r of feats[n,:] @ weight[k,:,:]^T
//
// Kernel 1: initialize out (n_out x 64) to bias, float4 stores.
// Kernel 2: per (k, tile of 64 points): load A tile (64x64) + W[k] (64x64, chunk-swizzled)
//           into SMEM, 4x4 register microtile per thread (256 thr), epilogue via
//           red.global.add.v4.f32 into scattered output rows.

#define CIN   64
#define COUT  64
#define TILE_N 64

__global__ void bias_init_kernel(float4* __restrict__ out4,
                                 const float4* __restrict__ bias4,
                                 int total4) {
    int i = blockIdx.x * blockDim.x + threadIdx.x;
    if (i < total4) {
        out4[i] = bias4[i & 15];   // 64 floats per row = 16 float4 chunks
    }
}

__global__ __launch_bounds__(256) void spconvt_gemm_scatter_kernel(
    const float* __restrict__ feats,     // [N, CIN]
    const float* __restrict__ weight,    // [KV, COUT, CIN]
    const int*   __restrict__ out_index, // [KV, N]
    float*       __restrict__ out,       // [n_out, COUT]
    int N)
{
    __shared__ float As[TILE_N][CIN];   // natural [point][cin]
    __shared__ float Ws[COUT][CIN];     // [cout][cin], chunk-XOR swizzled per row

    const int k   = blockIdx.y;
    const int n0  = blockIdx.x * TILE_N;
    const int tid = threadIdx.x;

    // ---- Load A tile: 64 rows x 16 float4, coalesced, zero-pad past N ----
    const float4* f4 = reinterpret_cast<const float4*>(feats);
    #pragma unroll
    for (int t = 0; t < 4; t++) {
        int idx = tid + t * 256;          // 0..1023
        int p = idx >> 4;                 // point within tile
        int q = idx & 15;                 // 16B chunk
        int n = n0 + p;
        float4 v = make_float4(0.f, 0.f, 0.f, 0.f);
        if (n < N) v = f4[n * 16 + q];
        *reinterpret_cast<float4*>(&As[p][q * 4]) = v;
    }

    // ---- Load W[k] with chunk swizzle: phys_chunk = q ^ ((c>>2)&7) ----
    const float4* w4 = reinterpret_cast<const float4*>(weight + (long)k * COUT * CIN);
    #pragma unroll
    for (int t = 0; t < 4; t++) {
        int idx = tid + t * 256;
        int c = idx >> 4;
        int q = idx & 15;
        float4 v = w4[idx];
        int qs = q ^ ((c >> 2) & 7);
        *reinterpret_cast<float4*>(&Ws[c][qs * 4]) = v;
    }
    __syncthreads();

    // ---- 4x4 microtile per thread: tc = channel group, tp = point group ----
    const int tc = tid & 15;
    const int tp = tid >> 4;
    const int c0 = tc * 4;
    const int p0 = tp * 4;

    float acc[4][4];
    #pragma unroll
    for (int a = 0; a < 4; a++)
        #pragma unroll
        for (int b = 0; b < 4; b++) acc[a][b] = 0.f;

    #pragma unroll 4
    for (int q = 0; q < 16; q++) {       // loop over CIN in 16B chunks
        float4 av[4], wv[4];
        #pragma unroll
        for (int j = 0; j < 4; j++)
            av[j] = *reinterpret_cast<const float4*>(&As[p0 + j][q * 4]);
        #pragma unroll
        for (int j = 0; j < 4; j++) {
            int c = c0 + j;
            int qs = q ^ ((c >> 2) & 7);
            wv[j] = *reinterpret_cast<const float4*>(&Ws[c][qs * 4]);
        }
        #pragma unroll
        for (int pj = 0; pj < 4; pj++) {
            #pragma unroll
            for (int cj = 0; cj < 4; cj++) {
                acc[pj][cj] += av[pj].x * wv[cj].x;
                acc[pj][cj] += av[pj].y * wv[cj].y;
                acc[pj][cj] += av[pj].z * wv[cj].z;
                acc[pj][cj] += av[pj].w * wv[cj].w;
            }
        }
    }

    // ---- Scatter epilogue: one vector reduction per point row ----
    const int* oi = out_index + (long)k * N + n0;
    #pragma unroll
    for (int pj = 0; pj < 4; pj++) {
        int n = n0 + p0 + pj;
        if (n < N) {
            int r = oi[p0 + pj];
            float* dst = out + (long)r * COUT + c0;   // 16B aligned (c0 % 4 == 0)
            asm volatile("red.global.add.v4.f32 [%0], {%1, %2, %3, %4};"
                         :: "l"(dst),
                            "f"(acc[pj][0]), "f"(acc[pj][1]),
                            "f"(acc[pj][2]), "f"(acc[pj][3])
                         : "memory");
        }
    }
}

extern "C" void kernel_launch(void* const* d_in, const int* in_sizes, int n_in,
                              void* d_out, int out_size) {
    const float* feats     = (const float*)d_in[0];   // [N, 64]
    const float* weight    = (const float*)d_in[1];   // [KV, 64, 64]
    const float* bias      = (const float*)d_in[2];   // [64]
    const int*   out_index = (const int*)d_in[3];     // [KV, N]
    float* out = (float*)d_out;                        // [n_out, 64]

    int N  = in_sizes[0] / CIN;
    int KV = in_sizes[1] / (COUT * CIN);

    // 1) out = bias (broadcast), float4 stores
    int total4 = out_size / 4;
    int ib = (total4 + 255) / 256;
    bias_init_kernel<<<ib, 256>>>((float4*)out, (const float4*)bias, total4);

    // 2) per-offset GEMM + scatter-add
    dim3 grid((N + TILE_N - 1) / TILE_N, KV);
    spconvt_gemm_scatter_kernel<<<grid, 256>>>(feats, weight, out_index, out, N);
}

// round 2
// speedup vs baseline: 1.0678x; 1.0678x over previous
#include <cuda_runtime.h>

// Sparse ConvTranspose3d on GB300 (sm_103a)
//   out[r,:] = bias + sum_{(k,n): out_index[k,n]==r} feats[n,:] @ weight[k,:,:]^T
//
// Kernel 1: out = bias broadcast (float4 stores, ~HBM write floor).
// Kernel 2: per (k, 128-point tile): A(128x64) + W[k](64x64) in SMEM,
//           8x8 register microtile per thread (128 threads) -> FFMA:LDS.128 = 16:1,
//           scatter epilogue via red.global.add.v4.f32.

#define CIN    64
#define COUT   64
#define TILE_N 128

__global__ void bias_init_kernel(float4* __restrict__ out4,
                                 const float4* __restrict__ bias4,
                                 int total4) {
    int i = blockIdx.x * blockDim.x + threadIdx.x;
    if (i < total4) {
        out4[i] = bias4[i & 15];   // 64 floats per row = 16 float4 chunks
    }
}

__global__ __launch_bounds__(128) void spconvt_gemm_scatter_kernel(
    const float* __restrict__ feats,     // [N, CIN]
    const float* __restrict__ weight,    // [KV, COUT, CIN]
    const int*   __restrict__ out_index, // [KV, N]
    float*       __restrict__ out,       // [n_out, COUT]
    int N)
{
    __shared__ float As[TILE_N][CIN];   // [point][cin], natural
    __shared__ float Ws[COUT][CIN];     // [cout][cin], chunk-swizzled: phys q = q ^ ((c>>3)&7)

    const int k   = blockIdx.y;
    const int n0  = blockIdx.x * TILE_N;
    const int tid = threadIdx.x;

    // ---- Load A tile: 128 rows x 16 float4 = 2048 float4, 16 iters ----
    const float4* f4 = reinterpret_cast<const float4*>(feats);
    #pragma unroll
    for (int t = 0; t < 16; t++) {
        int idx = tid + t * 128;          // 0..2047
        int p = idx >> 4;
        int q = idx & 15;
        int n = n0 + p;
        float4 v = make_float4(0.f, 0.f, 0.f, 0.f);
        if (n < N) v = f4[n * 16 + q];
        *reinterpret_cast<float4*>(&As[p][q * 4]) = v;
    }

    // ---- Load W[k]: 64 rows x 16 float4 = 1024 float4, 8 iters, swizzled ----
    const float4* w4 = reinterpret_cast<const float4*>(weight + (long)k * COUT * CIN);
    #pragma unroll
    for (int t = 0; t < 8; t++) {
        int idx = tid + t * 128;
        int c = idx >> 4;
        int q = idx & 15;
        float4 v = w4[idx];
        int qs = q ^ ((c >> 3) & 7);
        *reinterpret_cast<float4*>(&Ws[c][qs * 4]) = v;
    }
    __syncthreads();

    // ---- 8x8 microtile: tc = channel group (8 of them), tp = point group (16) ----
    const int tc = tid & 7;
    const int tp = tid >> 3;
    const int c0 = tc * 8;
    const int p0 = tp * 8;

    float acc[8][8];
    #pragma unroll
    for (int a = 0; a < 8; a++)
        #pragma unroll
        for (int b = 0; b < 8; b++) acc[a][b] = 0.f;

    // qs is constant per thread: (c0+cj)>>3 == tc for cj in [0,8)
    const int qsx = tc;   // XOR term

    #pragma unroll 2
    for (int q = 0; q < 16; q++) {       // CIN in 16B chunks
        float4 av[8];
        #pragma unroll
        for (int j = 0; j < 8; j++)
            av[j] = *reinterpret_cast<const float4*>(&As[p0 + j][q * 4]);

        int qs = q ^ qsx;
        #pragma unroll
        for (int cj = 0; cj < 8; cj++) {
            float4 wv = *reinterpret_cast<const float4*>(&Ws[c0 + cj][qs * 4]);
            #pragma unroll
            for (int pj = 0; pj < 8; pj++) {
                acc[pj][cj] += av[pj].x * wv.x;
                acc[pj][cj] += av[pj].y * wv.y;
                acc[pj][cj] += av[pj].z * wv.z;
                acc[pj][cj] += av[pj].w * wv.w;
            }
        }
    }

    // ---- Scatter epilogue: two v4 reductions per point row ----
    const int* oi = out_index + (long)k * N + n0;
    #pragma unroll
    for (int pj = 0; pj < 8; pj++) {
        int n = n0 + p0 + pj;
        if (n < N) {
            int r = oi[p0 + pj];
            float* dst = out + (long)r * COUT + c0;   // c0 % 8 == 0 -> 16B aligned
            asm volatile("red.global.add.v4.f32 [%0], {%1, %2, %3, %4};"
                         :: "l"(dst),
                            "f"(acc[pj][0]), "f"(acc[pj][1]),
                            "f"(acc[pj][2]), "f"(acc[pj][3])
                         : "memory");
            asm volatile("red.global.add.v4.f32 [%0], {%1, %2, %3, %4};"
                         :: "l"(dst + 4),
                            "f"(acc[pj][4]), "f"(acc[pj][5]),
                            "f"(acc[pj][6]), "f"(acc[pj][7])
                         : "memory");
        }
    }
}

extern "C" void kernel_launch(void* const* d_in, const int* in_sizes, int n_in,
                              void* d_out, int out_size) {
    const float* feats     = (const float*)d_in[0];   // [N, 64]
    const float* weight    = (const float*)d_in[1];   // [KV, 64, 64]
    const float* bias      = (const float*)d_in[2];   // [64]
    const int*   out_index = (const int*)d_in[3];     // [KV, N]
    float* out = (float*)d_out;                        // [n_out, 64]

    int N  = in_sizes[0] / CIN;
    int KV = in_sizes[1] / (COUT * CIN);

    // 1) out = bias (broadcast)
    int total4 = out_size / 4;
    int ib = (total4 + 255) / 256;
    bias_init_kernel<<<ib, 256>>>((float4*)out, (const float4*)bias, total4);

    // 2) per-offset GEMM + scatter-add
    dim3 grid((N + TILE_N - 1) / TILE_N, KV);
    spconvt_gemm_scatter_kernel<<<grid, 128>>>(feats, weight, out_index, out, N);
}